// round 17
// baseline (speedup 1.0000x reference)
#include <cuda_runtime.h>
#include <cuda_fp16.h>
#include <mma.h>
#include <cstdint>

using namespace nvcuda;

// ---------------- problem constants ----------------
#define B_    2
#define S_    2048
#define DIM_  5120
#define H_    40
#define KVH_  8
#define HD_   128
#define NREP_ 5
#define M_    (B_*S_)        // 4096
#define KVDIM_ (KVH_*HD_)    // 1024
#define QKV_N (DIM_ + 2*KVDIM_)   // 7168
#define WINDOW_ 1024
static const float SCALE_F = (float)(1.2079441541679836 / 11.313708498984760390); // mscale / sqrt(128)

// ---------------- scratch (device globals; no allocations allowed) ----------------
__device__ __align__(256) __half g_xh [(size_t)M_*DIM_];       // fp16 x
__device__ __align__(256) __half g_w1 [(size_t)DIM_*QKV_N];    // fp16 concat(wq|wk|wv)
__device__ __align__(256) __half g_wo [(size_t)DIM_*DIM_];     // fp16 wo
__device__ __align__(256) float  g_xqkv[(size_t)M_*QKV_N];     // QKV projection output (fp32)
__device__ __align__(256) __half g_q [(size_t)B_*H_*S_*HD_];   // fp16
__device__ __align__(256) __half g_k [(size_t)B_*KVH_*S_*HD_]; // fp16
__device__ __align__(256) __half g_v [(size_t)B_*KVH_*S_*HD_]; // fp16
__device__ __align__(256) __half g_attn[(size_t)M_*DIM_];      // fp16 attention out

__device__ __forceinline__ void cp_async16(void* dst_smem, const void* src_gmem)
{
    uint32_t d = (uint32_t)__cvta_generic_to_shared(dst_smem);
    asm volatile("cp.async.cg.shared.global [%0], [%1], 16;" :: "r"(d), "l"(src_gmem) : "memory");
}
#define CP_COMMIT() asm volatile("cp.async.commit_group;" ::: "memory")
#define CP_WAIT1()  asm volatile("cp.async.wait_group 1;" ::: "memory")

// ---------------- mma.sync helpers (shared by GEMM + attention) ----------------
__device__ __forceinline__ void ldsm_x4(uint32_t& r0, uint32_t& r1, uint32_t& r2, uint32_t& r3,
                                        uint32_t addr)
{
    asm volatile("ldmatrix.sync.aligned.m8n8.x4.shared.b16 {%0,%1,%2,%3}, [%4];"
                 : "=r"(r0), "=r"(r1), "=r"(r2), "=r"(r3) : "r"(addr));
}
__device__ __forceinline__ void ldsm_x4_t(uint32_t& r0, uint32_t& r1, uint32_t& r2, uint32_t& r3,
                                          uint32_t addr)
{
    asm volatile("ldmatrix.sync.aligned.m8n8.x4.trans.shared.b16 {%0,%1,%2,%3}, [%4];"
                 : "=r"(r0), "=r"(r1), "=r"(r2), "=r"(r3) : "r"(addr));
}
__device__ __forceinline__ void mma16816(float* c, uint32_t a0, uint32_t a1, uint32_t a2, uint32_t a3,
                                         uint32_t b0, uint32_t b1)
{
    asm volatile("mma.sync.aligned.m16n8k16.row.col.f32.f16.f16.f32 "
                 "{%0,%1,%2,%3}, {%4,%5,%6,%7}, {%8,%9}, {%0,%1,%2,%3};"
                 : "+f"(c[0]), "+f"(c[1]), "+f"(c[2]), "+f"(c[3])
                 : "r"(a0), "r"(a1), "r"(a2), "r"(a3), "r"(b0), "r"(b1));
}
__device__ __forceinline__ uint32_t f2h2(float a, float b)
{
    __half2 h = __floats2half2_rn(a, b);
    return *reinterpret_cast<uint32_t*>(&h);
}

// ================= fp16 raw-mma GEMM: CTA 128x256, warp 64x64, BK=32, 3-stage =================
// C[M,N] = A[M,K] @ B[K,N]; A,B fp16 row-major, C fp32. fp32 accumulate.
// 1 CTA/SM, 255-reg budget. 8 warps in 2(m) x 4(n).
#define GLDA 40                       // A stage leading dim (halves); 80 B/row
#define GLDB 264                      // B stage leading dim (halves); 528 B/row
#define GA_STG_H (128*GLDA)           // 5120 halves
#define GB_STG_H (32*GLDB)            // 8448 halves
#define GSTG_H   (GA_STG_H + GB_STG_H)
#define GNSTAGE  3
#define GEMM_SMEM (GNSTAGE*GSTG_H*2)  // 81,408 B

__global__ __launch_bounds__(256, 1) void gemm_f16(const __half* __restrict__ A,
                                                   const __half* __restrict__ Bm,
                                                   float* __restrict__ C,
                                                   int N, int K)
{
    extern __shared__ __half smem_h[];
    const int tid  = threadIdx.x;
    const int w    = tid >> 5;
    const int lane = tid & 31;
    const int gid  = lane >> 2;
    const int qd   = lane & 3;
    const int wm0  = (w & 1) * 64;    // warp row base within CTA tile
    const int wn0  = (w >> 1) * 64;   // warp col base within CTA tile
    const int bm0  = blockIdx.y * 128;
    const int bn0  = blockIdx.x * 256;
    const int NK   = K >> 5;          // K/32 stages

    float acc[4][8][4];
    #pragma unroll
    for (int mt = 0; mt < 4; mt++)
        #pragma unroll
        for (int nt = 0; nt < 8; nt++)
            #pragma unroll
            for (int e = 0; e < 4; e++) acc[mt][nt][e] = 0.0f;

    // stage loader: A 512 chunks + B 1024 chunks = 1536, 6 per thread
    auto issue_stage = [&](int s, int k0) {
        __half* as = smem_h + s * GSTG_H;
        __half* bs = as + GA_STG_H;
        #pragma unroll
        for (int t = 0; t < 6; t++) {
            int idx = tid + t * 256;
            if (idx < 512) {                       // A: 128 rows x 4 chunks (8 halves)
                int m = idx >> 2, c = (idx & 3) << 3;
                cp_async16(as + m * GLDA + c, A + (size_t)(bm0 + m) * K + k0 + c);
            } else {                               // B: 32 k-rows x 32 chunks
                int j = idx - 512;
                int kr = j >> 5, c = (j & 31) << 3;
                cp_async16(bs + kr * GLDB + c, Bm + (size_t)(k0 + kr) * N + bn0 + c);
            }
        }
    };

    issue_stage(0, 0);
    CP_COMMIT();
    issue_stage(1, 32);
    CP_COMMIT();

    const uint32_t smem_u = (uint32_t)__cvta_generic_to_shared(smem_h);
    // ldmatrix lane address pattern (rows from lane&7 + ((lane>>3)&1)*8; +16B for lanes>=16):
    // non-trans on row-major [m][k] yields a0..a3 in exact m16n8k16 A order;
    // trans on row-major [k][n] yields (b0,b1)=n-tile j, (b2,b3)=n-tile j+1.
    const uint32_t laddrA = (uint32_t)((((lane >> 3) & 1) * 8 + (lane & 7)) * (GLDA * 2)
                                       + ((lane >> 4) & 1) * 16);
    const uint32_t laddrB = (uint32_t)((((lane >> 3) & 1) * 8 + (lane & 7)) * (GLDB * 2)
                                       + ((lane >> 4) & 1) * 16);

    for (int i = 0; i < NK; i++) {
        CP_WAIT1();
        __syncthreads();

        const uint32_t as_u = smem_u + (uint32_t)((i % GNSTAGE) * GSTG_H * 2);
        const uint32_t bs_u = as_u + (uint32_t)(GA_STG_H * 2);

        #pragma unroll
        for (int ks = 0; ks < 2; ks++) {           // two k16 substeps per BK=32
            uint32_t af[4][4];
            #pragma unroll
            for (int mt = 0; mt < 4; mt++)
                ldsm_x4(af[mt][0], af[mt][1], af[mt][2], af[mt][3],
                        as_u + laddrA + (uint32_t)((wm0 + mt * 16) * (GLDA * 2) + ks * 32));
            uint32_t bf[4][4];
            #pragma unroll
            for (int np = 0; np < 4; np++)
                ldsm_x4_t(bf[np][0], bf[np][1], bf[np][2], bf[np][3],
                          bs_u + laddrB + (uint32_t)(ks * 16 * (GLDB * 2) + (wn0 + np * 16) * 2));
            #pragma unroll
            for (int mt = 0; mt < 4; mt++)
                #pragma unroll
                for (int np = 0; np < 4; np++) {
                    mma16816(acc[mt][2 * np],     af[mt][0], af[mt][1], af[mt][2], af[mt][3],
                             bf[np][0], bf[np][1]);
                    mma16816(acc[mt][2 * np + 1], af[mt][0], af[mt][1], af[mt][2], af[mt][3],
                             bf[np][2], bf[np][3]);
                }
        }

        const int nx = i + 2;
        if (nx < NK) issue_stage(nx % GNSTAGE, nx * 32);
        CP_COMMIT();
    }

    // epilogue: direct float2 stores from c-frags
    #pragma unroll
    for (int mt = 0; mt < 4; mt++) {
        const int row0 = bm0 + wm0 + mt * 16 + gid;
        #pragma unroll
        for (int nt = 0; nt < 8; nt++) {
            const int col = bn0 + wn0 + nt * 8 + qd * 2;
            *(float2*)(C + (size_t)row0 * N + col)       = make_float2(acc[mt][nt][0], acc[mt][nt][1]);
            *(float2*)(C + (size_t)(row0 + 8) * N + col) = make_float2(acc[mt][nt][2], acc[mt][nt][3]);
        }
    }
}

// ================= fp32 -> fp16 conversion passes =================
__global__ __launch_bounds__(256) void conv_half(__half* __restrict__ dst,
                                                 const float* __restrict__ src, int n4)
{
    int i = blockIdx.x * 256 + threadIdx.x;
    if (i >= n4) return;
    float4 v = ((const float4*)src)[i];
    __half2* d = (__half2*)(dst + (size_t)i * 4);
    d[0] = __floats2half2_rn(v.x, v.y);
    d[1] = __floats2half2_rn(v.z, v.w);
}

__global__ __launch_bounds__(256) void conv_concat_w(const float* __restrict__ wq,
                                                     const float* __restrict__ wk,
                                                     const float* __restrict__ wv)
{
    int i = blockIdx.x * 256 + threadIdx.x;
    const int n4 = DIM_ * QKV_N / 4;
    if (i >= n4) return;
    int c = (i % (QKV_N / 4)) * 4;
    int d = i / (QKV_N / 4);
    const float* src;
    if (c < DIM_)                 src = wq + (size_t)d * DIM_   + c;
    else if (c < DIM_ + KVDIM_)   src = wk + (size_t)d * KVDIM_ + (c - DIM_);
    else                          src = wv + (size_t)d * KVDIM_ + (c - DIM_ - KVDIM_);
    float4 v = *(const float4*)src;
    __half2* dp = (__half2*)(g_w1 + (size_t)i * 4);
    dp[0] = __floats2half2_rn(v.x, v.y);
    dp[1] = __floats2half2_rn(v.z, v.w);
}

// ---------------- block sum helper ----------------
__device__ __forceinline__ float block_sum_256(float v, float* red8)
{
    #pragma unroll
    for (int o = 16; o > 0; o >>= 1) v += __shfl_xor_sync(0xffffffffu, v, o);
    if ((threadIdx.x & 31) == 0) red8[threadIdx.x >> 5] = v;
    __syncthreads();
    float total = 0.0f;
    #pragma unroll
    for (int i = 0; i < 8; i++) total += red8[i];
    return total;
}

// ---------------- RMSNorm(5120) + RoPE on Q, re-layout to [b,h,s,d], fp16 out ----------------
__global__ __launch_bounds__(256) void qnorm_rope_kernel(const float* __restrict__ qw,
                                                         const float* __restrict__ cos_h,
                                                         const float* __restrict__ sin_h)
{
    __shared__ float red8[8];
    const int row = blockIdx.x;
    const int b = row >> 11;
    const int s = row & (S_ - 1);
    const float* xr = g_xqkv + (size_t)row * QKV_N;

    float ss = 0.0f;
    for (int i = threadIdx.x; i < DIM_; i += 256) { float v = xr[i]; ss += v * v; }
    float total = block_sum_256(ss, red8);
    const float rms = rsqrtf(total / (float)DIM_ + 1e-6f);

    for (int idx = threadIdx.x; idx < H_ * 64; idx += 256) {
        int h = idx >> 6;
        int d = idx & 63;
        float x1 = xr[h * HD_ + d]      * rms * qw[h * HD_ + d];
        float x2 = xr[h * HD_ + d + 64] * rms * qw[h * HD_ + d + 64];
        float c  = cos_h[s * 64 + d];
        float sn = sin_h[s * 64 + d];
        __half* o = g_q + ((size_t)(b * H_ + h) * S_ + s) * HD_;
        o[d]      = __float2half_rn(x1 * c - x2 * sn);
        o[d + 64] = __float2half_rn(x2 * c + x1 * sn);
    }
}

// ---------------- RMSNorm(1024) + RoPE on K, copy/relayout V, fp16 out ----------------
__global__ __launch_bounds__(256) void knorm_rope_v_kernel(const float* __restrict__ kw,
                                                           const float* __restrict__ cos_h,
                                                           const float* __restrict__ sin_h)
{
    __shared__ float red8[8];
    const int row = blockIdx.x;
    const int b = row >> 11;
    const int s = row & (S_ - 1);
    const float* xk = g_xqkv + (size_t)row * QKV_N + DIM_;
    const float* xv = g_xqkv + (size_t)row * QKV_N + DIM_ + KVDIM_;

    float ss = 0.0f;
    for (int i = threadIdx.x; i < KVDIM_; i += 256) { float v = xk[i]; ss += v * v; }
    float total = block_sum_256(ss, red8);
    const float rms = rsqrtf(total / (float)KVDIM_ + 1e-6f);

    for (int idx = threadIdx.x; idx < KVH_ * 64; idx += 256) {
        int h = idx >> 6;
        int d = idx & 63;
        float x1 = xk[h * HD_ + d]      * rms * kw[h * HD_ + d];
        float x2 = xk[h * HD_ + d + 64] * rms * kw[h * HD_ + d + 64];
        float c  = cos_h[s * 64 + d];
        float sn = sin_h[s * 64 + d];
        __half* o = g_k + ((size_t)(b * KVH_ + h) * S_ + s) * HD_;
        o[d]      = __float2half_rn(x1 * c - x2 * sn);
        o[d + 64] = __float2half_rn(x2 * c + x1 * sn);
    }
    for (int idx = threadIdx.x; idx < KVDIM_; idx += 256) {
        int h = idx >> 7;
        int d = idx & 127;
        g_v[((size_t)(b * KVH_ + h) * S_ + s) * HD_ + d] = __float2half_rn(xv[idx]);
    }
}

// ============ flash attention: raw mma.sync, register-resident S/P/O, QT=128 ============
#define QT2   128
#define KT2   64
#define ALD   136                                  // K/V tile leading dim (halves)
#define KVTILE_H (KT2 * ALD)                       // 8704 halves
#define ATT_SMEM_BYTES (4 * KVTILE_H * 2)          // 69,632 B (K dbl + V dbl)

__global__ __launch_bounds__(256, 1) void attn_kernel()
{
    extern __shared__ __half smemh[];
    __half* Ks0 = smemh;                           // 2 x 64x136
    __half* Vs0 = Ks0 + 2 * KVTILE_H;              // 2 x 64x136

    const int q0   = blockIdx.x * QT2;
    const int h    = blockIdx.y;
    const int b    = blockIdx.z;
    const int kvh  = h / NREP_;
    const int tid  = threadIdx.x;
    const int w    = tid >> 5;
    const int lane = tid & 31;
    const int gid  = lane >> 2;
    const int qd   = lane & 3;

    const __half* Qg = g_q + ((size_t)(b * H_ + h) * S_ + q0) * HD_;
    const __half* Kg = g_k + ((size_t)(b * KVH_ + kvh) * S_) * HD_;
    const __half* Vg = g_v + ((size_t)(b * KVH_ + kvh) * S_) * HD_;

    auto issue_kv = [&](int buf, int j0) {
        __half* ks = Ks0 + buf * KVTILE_H;
        __half* vs = Vs0 + buf * KVTILE_H;
        #pragma unroll
        for (int t = 0; t < 8; t++) {
            int idx = tid + t * 256;
            int r = (idx >> 4) & 63, c = (idx & 15) << 3;
            if (idx < 1024) cp_async16(ks + r * ALD + c, Kg + (size_t)(j0 + r) * HD_ + c);
            else            cp_async16(vs + r * ALD + c, Vg + (size_t)(j0 + r) * HD_ + c);
        }
    };

    uint32_t qa[8][4];
    {
        const __half* r0p = Qg + (size_t)(w * 16 + gid) * HD_ + qd * 2;
        const __half* r1p = r0p + 8 * HD_;
        #pragma unroll
        for (int kt = 0; kt < 8; kt++) {
            qa[kt][0] = *(const uint32_t*)(r0p + kt * 16);
            qa[kt][1] = *(const uint32_t*)(r1p + kt * 16);
            qa[kt][2] = *(const uint32_t*)(r0p + kt * 16 + 8);
            qa[kt][3] = *(const uint32_t*)(r1p + kt * 16 + 8);
        }
    }

    float o[16][4];
    #pragma unroll
    for (int jt = 0; jt < 16; jt++)
        #pragma unroll
        for (int e = 0; e < 4; e++) o[jt][e] = 0.0f;
    float rm0 = -1e30f, rm1 = -1e30f, rl0 = 0.0f, rl1 = 0.0f;

    const int jstart = (q0 >= WINDOW_) ? (q0 - WINDOW_) : 0;
    issue_kv(0, jstart);
    CP_COMMIT();
    if (jstart + KT2 < q0 + QT2) issue_kv(1, jstart + KT2);
    CP_COMMIT();

    const uint32_t ks_u0 = (uint32_t)__cvta_generic_to_shared(Ks0);
    const uint32_t vs_u0 = (uint32_t)__cvta_generic_to_shared(Vs0);
    const uint32_t laddrQK = (uint32_t)((((lane >> 4) & 1) * 8 + (lane & 7)) * (ALD * 2)
                                        + ((lane >> 3) & 1) * 16);
    const uint32_t laddrPV = (uint32_t)((((lane >> 3) & 1) * 8 + (lane & 7)) * (ALD * 2)
                                        + ((lane >> 4) & 1) * 16);
    const int gi0 = q0 + w * 16 + gid;
    const int gi1 = gi0 + 8;

    int t_idx = 0;
    for (int j0 = jstart; j0 < q0 + QT2; j0 += KT2, t_idx++) {
        const int buf = t_idx & 1;
        CP_WAIT1();
        __syncthreads();

        const uint32_t ksb = ks_u0 + (uint32_t)(buf * KVTILE_H * 2) + laddrQK;
        const uint32_t vsb = vs_u0 + (uint32_t)(buf * KVTILE_H * 2) + laddrPV;

        float sacc[8][4];
        #pragma unroll
        for (int nt = 0; nt < 8; nt++)
            #pragma unroll
            for (int e = 0; e < 4; e++) sacc[nt][e] = 0.0f;

        #pragma unroll
        for (int kt = 0; kt < 8; kt++) {
            #pragma unroll
            for (int ntp = 0; ntp < 4; ntp++) {
                uint32_t b0, b1, b2, b3;
                ldsm_x4(b0, b1, b2, b3, ksb + (uint32_t)(ntp * (16 * ALD * 2) + kt * 32));
                mma16816(sacc[2 * ntp],     qa[kt][0], qa[kt][1], qa[kt][2], qa[kt][3], b0, b1);
                mma16816(sacc[2 * ntp + 1], qa[kt][0], qa[kt][1], qa[kt][2], qa[kt][3], b2, b3);
            }
        }

        float mx0 = -1e30f, mx1 = -1e30f;
        #pragma unroll
        for (int nt = 0; nt < 8; nt++) {
            int gj = j0 + nt * 8 + qd * 2;
            #pragma unroll
            for (int e = 0; e < 2; e++) {
                int gjj = gj + e;
                bool ok0 = (gjj <= gi0) && (gi0 - gjj <= WINDOW_);
                bool ok1 = (gjj <= gi1) && (gi1 - gjj <= WINDOW_);
                float v0 = ok0 ? sacc[nt][e]     * SCALE_F : -1e30f;
                float v1 = ok1 ? sacc[nt][2 + e] * SCALE_F : -1e30f;
                sacc[nt][e] = v0; sacc[nt][2 + e] = v1;
                mx0 = fmaxf(mx0, v0); mx1 = fmaxf(mx1, v1);
            }
        }
        mx0 = fmaxf(mx0, __shfl_xor_sync(0xffffffffu, mx0, 1));
        mx0 = fmaxf(mx0, __shfl_xor_sync(0xffffffffu, mx0, 2));
        mx1 = fmaxf(mx1, __shfl_xor_sync(0xffffffffu, mx1, 1));
        mx1 = fmaxf(mx1, __shfl_xor_sync(0xffffffffu, mx1, 2));
        const float mn0 = fmaxf(rm0, mx0), mn1 = fmaxf(rm1, mx1);
        const float al0 = __expf(rm0 - mn0), al1 = __expf(rm1 - mn1);
        float s0 = 0.0f, s1 = 0.0f;
        #pragma unroll
        for (int nt = 0; nt < 8; nt++) {
            #pragma unroll
            for (int e = 0; e < 2; e++) {
                float p0 = (sacc[nt][e]     > -5e29f) ? __expf(sacc[nt][e]     - mn0) : 0.0f;
                float p1 = (sacc[nt][2 + e] > -5e29f) ? __expf(sacc[nt][2 + e] - mn1) : 0.0f;
                sacc[nt][e] = p0; sacc[nt][2 + e] = p1;
                s0 += p0; s1 += p1;
            }
        }
        s0 += __shfl_xor_sync(0xffffffffu, s0, 1);
        s0 += __shfl_xor_sync(0xffffffffu, s0, 2);
        s1 += __shfl_xor_sync(0xffffffffu, s1, 1);
        s1 += __shfl_xor_sync(0xffffffffu, s1, 2);
        rl0 = rl0 * al0 + s0; rl1 = rl1 * al1 + s1;
        rm0 = mn0; rm1 = mn1;

        #pragma unroll
        for (int jt = 0; jt < 16; jt++) {
            o[jt][0] *= al0; o[jt][1] *= al0;
            o[jt][2] *= al1; o[jt][3] *= al1;
        }

        #pragma unroll
        for (int kt2 = 0; kt2 < 4; kt2++) {
            uint32_t a0 = f2h2(sacc[2 * kt2][0],     sacc[2 * kt2][1]);
            uint32_t a1 = f2h2(sacc[2 * kt2][2],     sacc[2 * kt2][3]);
            uint32_t a2 = f2h2(sacc[2 * kt2 + 1][0], sacc[2 * kt2 + 1][1]);
            uint32_t a3 = f2h2(sacc[2 * kt2 + 1][2], sacc[2 * kt2 + 1][3]);
            #pragma unroll
            for (int jtp = 0; jtp < 8; jtp++) {
                uint32_t b0, b1, b2, b3;
                ldsm_x4_t(b0, b1, b2, b3, vsb + (uint32_t)(kt2 * (16 * ALD * 2) + jtp * 32));
                mma16816(o[2 * jtp],     a0, a1, a2, a3, b0, b1);
                mma16816(o[2 * jtp + 1], a0, a1, a2, a3, b2, b3);
            }
        }

        __syncthreads();
        if (j0 + 2 * KT2 < q0 + QT2) issue_kv(buf, j0 + 2 * KT2);
        CP_COMMIT();
    }

    const float inv0 = 1.0f / rl0, inv1 = 1.0f / rl1;
    __half* orow0 = g_attn + ((size_t)(b * S_) + q0 + w * 16 + gid) * DIM_ + h * HD_ + qd * 2;
    __half* orow1 = orow0 + (size_t)8 * DIM_;
    #pragma unroll
    for (int jt = 0; jt < 16; jt++) {
        *(uint32_t*)(orow0 + jt * 8) = f2h2(o[jt][0] * inv0, o[jt][1] * inv0);
        *(uint32_t*)(orow1 + jt * 8) = f2h2(o[jt][2] * inv1, o[jt][3] * inv1);
    }
}

// ---------------- launch ----------------
extern "C" void kernel_launch(void* const* d_in, const int* in_sizes, int n_in,
                              void* d_out, int out_size)
{
    (void)in_sizes; (void)n_in; (void)out_size;
    const float* x     = (const float*)d_in[0];
    const float* wq    = (const float*)d_in[1];
    const float* wk    = (const float*)d_in[2];
    const float* wv    = (const float*)d_in[3];
    const float* wo    = (const float*)d_in[4];
    const float* qw    = (const float*)d_in[5];
    const float* kw    = (const float*)d_in[6];
    const float* cosh_ = (const float*)d_in[7];
    const float* sinh_ = (const float*)d_in[8];
    float* out = (float*)d_out;

    __half *p_xh, *p_w1, *p_wo, *p_attn;
    float  *p_xqkv;
    cudaGetSymbolAddress((void**)&p_xh,   g_xh);
    cudaGetSymbolAddress((void**)&p_w1,   g_w1);
    cudaGetSymbolAddress((void**)&p_wo,   g_wo);
    cudaGetSymbolAddress((void**)&p_xqkv, g_xqkv);
    cudaGetSymbolAddress((void**)&p_attn, g_attn);

    cudaFuncSetAttribute(gemm_f16,    cudaFuncAttributeMaxDynamicSharedMemorySize, GEMM_SMEM);
    cudaFuncSetAttribute(attn_kernel, cudaFuncAttributeMaxDynamicSharedMemorySize, ATT_SMEM_BYTES);

    // fp32 -> fp16 RN conversions
    {
        int n4x = M_ * DIM_ / 4;
        conv_half<<<(n4x + 255) / 256, 256>>>(p_xh, x, n4x);
        int n4w = DIM_ * QKV_N / 4;
        conv_concat_w<<<(n4w + 255) / 256, 256>>>(wq, wk, wv);
        int n4o = DIM_ * DIM_ / 4;
        conv_half<<<(n4o + 255) / 256, 256>>>(p_wo, wo, n4o);
    }

    // fused QKV projection: [4096, 7168] = x_h @ concat(wq|wk|wv)
    gemm_f16<<<dim3(QKV_N / 256, M_ / 128), 256, GEMM_SMEM>>>(p_xh, p_w1, p_xqkv, QKV_N, DIM_);

    // norms + rope + relayout (outputs fp16)
    qnorm_rope_kernel<<<M_, 256>>>(qw, cosh_, sinh_);
    knorm_rope_v_kernel<<<M_, 256>>>(kw, cosh_, sinh_);

    // attention (raw mma.sync, QT=128)
    attn_kernel<<<dim3(S_ / QT2, H_, B_), 256, ATT_SMEM_BYTES>>>();

    // output projection
    gemm_f16<<<dim3(DIM_ / 256, M_ / 128), 256, GEMM_SMEM>>>(p_attn, p_wo, out, DIM_, DIM_);
}